// round 4
// baseline (speedup 1.0000x reference)
#include <cuda_runtime.h>
#include <math.h>

// Problem constants (fixed by the reference)
#define NN    1536   // nodes
#define DEG   32     // candidate out-degree per node
#define BS    8      // sequential batch steps
#define OBSD  33
#define HIDN  64
#define NH    4      // heads
#define CD    8      // channels per head
#define KS    4      // top-k
#define EMB   32
#define ATTN_OFS ((size_t)BS * NN * EMB)   // outs precede attns in d_out

#define RTB 8   // rows per block in embed
#define GNT 8   // nodes per block in gru
#define PNT 8   // (t,node) pairs per block in post

// -------- persistent device scratch (no allocations allowed) --------
__device__ float g_Hemb[BS * NN * EMB];
__device__ float g_h[NN * HIDN];
__device__ float g_hall[BS * NN * HIDN];
__device__ float g_P[BS * NN * HIDN];
__device__ float g_Q[BS * NN * HIDN];
__device__ float g_xh[BS * NN * EMB];
__device__ float g_as[BS * NN * NH];
__device__ float g_ad[BS * NN * NH];
__device__ int   g_kdst[BS * NN * KS];
__device__ float g_kw[BS * NN * KS];
__device__ float g_kex[BS * NN * KS * NH];
__device__ float g_ssum[BS * NN * NH];
__device__ float g_Aval[BS * NN * KS * NH];  // normalized, dedup-merged A entries
__device__ int   g_Adst[BS * NN * KS];       // -1 = duplicate slot (skip)

__device__ __forceinline__ float sigm(float x) { return 1.f / (1.f + expf(-x)); }

// ---------------- zero-fill the whole attention output region ----------------
__global__ void zeroA(float* __restrict__ outp) {
    float4* base = (float4*)(outp + ATTN_OFS);
    size_t total = (size_t)BS * NH * NN * NN / 4;
    size_t stride = (size_t)gridDim.x * blockDim.x;
    float4 z = make_float4(0.f, 0.f, 0.f, 0.f);
    for (size_t i = (size_t)blockIdx.x * blockDim.x + threadIdx.x; i < total; i += stride)
        base[i] = z;
}

// ---------------- Obs embedding: Linear-ReLU-Linear-ReLU-LayerNorm ----------------
// grid = B*N/RTB blocks, 32 threads; each thread computes channel j for RTB rows.
__global__ void embed_k(const float* __restrict__ Ht,
                        const float* __restrict__ We1, const float* __restrict__ be1,
                        const float* __restrict__ We2, const float* __restrict__ be2,
                        const float* __restrict__ lng, const float* __restrict__ lnb) {
    int r0 = blockIdx.x * RTB;
    int j  = threadIdx.x;  // 0..31
    __shared__ float in_s[RTB][OBSD + 1];
    __shared__ float x1_s[RTB][EMB];

    for (int t = j; t < RTB * OBSD; t += 32)
        in_s[t / OBSD][t % OBSD] = Ht[(size_t)r0 * OBSD + t];
    __syncwarp();

    float a[RTB];
    float b1 = be1[j];
#pragma unroll
    for (int m = 0; m < RTB; m++) a[m] = b1;
#pragma unroll
    for (int k = 0; k < OBSD; k++) {
        float w = We1[k * EMB + j];
#pragma unroll
        for (int m = 0; m < RTB; m++) a[m] += in_s[m][k] * w;
    }
#pragma unroll
    for (int m = 0; m < RTB; m++) x1_s[m][j] = fmaxf(a[m], 0.f);
    __syncwarp();

    float b[RTB];
    float b2 = be2[j];
#pragma unroll
    for (int m = 0; m < RTB; m++) b[m] = b2;
#pragma unroll
    for (int k = 0; k < EMB; k++) {
        float w = We2[k * EMB + j];
#pragma unroll
        for (int m = 0; m < RTB; m++) b[m] += x1_s[m][k] * w;
    }

    float gj = lng[j], bj = lnb[j];
#pragma unroll
    for (int m = 0; m < RTB; m++) {
        float x = fmaxf(b[m], 0.f);
        float s = x;
#pragma unroll
        for (int o = 16; o; o >>= 1) s += __shfl_xor_sync(0xffffffffu, s, o);
        float mu = s * (1.f / 32.f);
        float d  = x - mu;
        float v  = d * d;
#pragma unroll
        for (int o = 16; o; o >>= 1) v += __shfl_xor_sync(0xffffffffu, v, o);
        g_Hemb[(size_t)(r0 + m) * EMB + j] = d * rsqrtf(v * (1.f / 32.f) + 1e-5f) * gj + bj;
    }
}

// ---------------- GRU (the only serial kernel): h -> h_new, stored per step ----------------
// grid = N/GNT blocks, 64 threads; each thread computes output j for GNT nodes.
__global__ void gru_k(int step,
                      const float* __restrict__ Wih, const float* __restrict__ Whh,
                      const float* __restrict__ bih, const float* __restrict__ bhh) {
    int n0 = blockIdx.x * GNT;
    int j  = threadIdx.x;  // 0..63
    __shared__ float e_s[GNT][EMB];
    __shared__ float h_s[GNT][HIDN];

    for (int t = j; t < GNT * EMB; t += 64)
        e_s[t >> 5][t & 31] = g_Hemb[((size_t)step * NN + n0) * EMB + t];
    for (int t = j; t < GNT * HIDN; t += 64)
        h_s[t >> 6][t & 63] = (step == 0) ? 0.f : g_h[(size_t)n0 * HIDN + t];
    __syncthreads();

    float rg[GNT], zg[GNT], hn[GNT];
#pragma unroll
    for (int g = 0; g < 3; g++) {
        float bi = bih[g * HIDN + j];
        float bh = bhh[g * HIDN + j];
        float ai[GNT], ah[GNT];
#pragma unroll
        for (int m = 0; m < GNT; m++) { ai[m] = bi; ah[m] = bh; }
        const float4* wi = (const float4*)(Wih + (size_t)(g * HIDN + j) * EMB);
#pragma unroll
        for (int k4 = 0; k4 < EMB / 4; k4++) {
            float4 w = wi[k4];
            int k = k4 * 4;
#pragma unroll
            for (int m = 0; m < GNT; m++)
                ai[m] += e_s[m][k] * w.x + e_s[m][k + 1] * w.y + e_s[m][k + 2] * w.z + e_s[m][k + 3] * w.w;
        }
        const float4* wh = (const float4*)(Whh + (size_t)(g * HIDN + j) * HIDN);
#pragma unroll
        for (int k4 = 0; k4 < HIDN / 4; k4++) {
            float4 w = wh[k4];
            int k = k4 * 4;
#pragma unroll
            for (int m = 0; m < GNT; m++)
                ah[m] += h_s[m][k] * w.x + h_s[m][k + 1] * w.y + h_s[m][k + 2] * w.z + h_s[m][k + 3] * w.w;
        }
        if (g == 0) {
#pragma unroll
            for (int m = 0; m < GNT; m++) rg[m] = sigm(ai[m] + ah[m]);
        } else if (g == 1) {
#pragma unroll
            for (int m = 0; m < GNT; m++) zg[m] = sigm(ai[m] + ah[m]);
        } else {
#pragma unroll
            for (int m = 0; m < GNT; m++) {
                float nv = tanhf(ai[m] + rg[m] * ah[m]);
                hn[m] = (1.f - zg[m]) * nv + zg[m] * h_s[m][j];
            }
        }
    }
#pragma unroll
    for (int m = 0; m < GNT; m++) {
        g_h[(size_t)(n0 + m) * HIDN + j] = hn[m];
        g_hall[((size_t)step * NN + n0 + m) * HIDN + j] = hn[m];
    }
}

// ---------------- post_all: P/Q/xh/a_s/a_d + inits for ALL steps at once ----------------
// grid = BS*N/PNT blocks, 64 threads.
__global__ void post_k(const float* __restrict__ Ws1, const float* __restrict__ bs1,
                       const float* __restrict__ Wgat,
                       const float* __restrict__ asrc, const float* __restrict__ adst,
                       const float* __restrict__ bgat,
                       float* __restrict__ outp) {
    size_t r0 = (size_t)blockIdx.x * PNT;   // flat (t*NN+n) index
    int j = threadIdx.x;                    // 0..63
    __shared__ float hn_s[PNT][HIDN];
    __shared__ float xh_s[PNT][EMB];

    for (int t = j; t < PNT * HIDN; t += 64)
        hn_s[t >> 6][t & 63] = g_hall[r0 * HIDN + t];
    __syncthreads();

    float p[PNT], q[PNT];
    float bp = bs1[j];
#pragma unroll
    for (int m = 0; m < PNT; m++) { p[m] = bp; q[m] = 0.f; }
#pragma unroll 8
    for (int k = 0; k < HIDN; k++) {
        float w1 = Ws1[k * HIDN + j];
        float w2 = Ws1[(HIDN + k) * HIDN + j];
#pragma unroll
        for (int m = 0; m < PNT; m++) { p[m] += hn_s[m][k] * w1; q[m] += hn_s[m][k] * w2; }
    }
#pragma unroll
    for (int m = 0; m < PNT; m++) {
        g_P[(r0 + m) * HIDN + j] = p[m];
        g_Q[(r0 + m) * HIDN + j] = q[m];
    }

    if (j < EMB) {
        float x[PNT];
#pragma unroll
        for (int m = 0; m < PNT; m++) x[m] = 0.f;
#pragma unroll 8
        for (int k = 0; k < HIDN; k++) {
            float w = Wgat[k * EMB + j];
#pragma unroll
            for (int m = 0; m < PNT; m++) x[m] += hn_s[m][k] * w;
        }
        float bg = bgat[j];
#pragma unroll
        for (int m = 0; m < PNT; m++) {
            xh_s[m][j] = x[m];
            g_xh[(r0 + m) * EMB + j] = x[m];
            outp[(r0 + m) * EMB + j] = bg;  // segment_sum init + bias
        }
    }
    __syncthreads();

    if (j < PNT * NH) {
        int m = j >> 2, h = j & 3;
        float as_ = 0.f, ad_ = 0.f;
#pragma unroll
        for (int c = 0; c < CD; c++) {
            as_ += xh_s[m][h * CD + c] * asrc[h * CD + c];
            ad_ += xh_s[m][h * CD + c] * adst[h * CD + c];
        }
        g_as[(r0 + m) * NH + h]   = as_;
        g_ad[(r0 + m) * NH + h]   = ad_;
        g_ssum[(r0 + m) * NH + h] = 0.f;
    }
}

// ---------------- k2_all: edge scores + warp top-k + exp + segment sums (all steps) ----------------
// grid = BS*N/8 blocks, 256 threads (one warp per (t, src)).
__global__ void k2_all(const int* __restrict__ dst,
                       const float* __restrict__ Ws2, const float* __restrict__ bs2) {
    int warp = threadIdx.x >> 5, lane = threadIdx.x & 31;
    size_t b = (size_t)blockIdx.x * 8 + warp;   // flat (t*NN + n)
    int n = (int)(b % NN);
    size_t tbase = b - n;                        // t*NN

    __shared__ float w2_s[HIDN];
    __shared__ float P_sh[8][HIDN];
    if (threadIdx.x < HIDN) w2_s[threadIdx.x] = Ws2[threadIdx.x];
    P_sh[warp][lane]      = g_P[b * HIDN + lane];
    P_sh[warp][32 + lane] = g_P[b * HIDN + 32 + lane];
    float as0 = g_as[b * NH + 0], as1 = g_as[b * NH + 1];
    float as2 = g_as[b * NH + 2], as3 = g_as[b * NH + 3];
    __syncthreads();

    int d = dst[n * DEG + lane];
    const float4* Qr = (const float4*)(g_Q + (tbase + d) * HIDN);
    float acc = bs2[0];
    const float* P_s = P_sh[warp];
#pragma unroll
    for (int k4 = 0; k4 < HIDN / 4; k4++) {
        float4 qv = Qr[k4];
        int k = k4 * 4;
        acc += fmaxf(P_s[k] + qv.x, 0.f) * w2_s[k]
             + fmaxf(P_s[k + 1] + qv.y, 0.f) * w2_s[k + 1]
             + fmaxf(P_s[k + 2] + qv.z, 0.f) * w2_s[k + 2]
             + fmaxf(P_s[k + 3] + qv.w, 0.f) * w2_s[k + 3];
    }
    float score = sigm(acc);

    // top-k (k=4) among 32 lanes; ties -> lower index (matches jax.lax.top_k)
    bool sel = false;
#pragma unroll
    for (int r = 0; r < KS; r++) {
        float v = sel ? -1e30f : score;
        int   idx = lane;
#pragma unroll
        for (int o = 16; o; o >>= 1) {
            float ov = __shfl_xor_sync(0xffffffffu, v, o);
            int   oi = __shfl_xor_sync(0xffffffffu, idx, o);
            if (ov > v || (ov == v && oi < idx)) { v = ov; idx = oi; }
        }
        if (lane == idx) sel = true;
    }
    unsigned ball = __ballot_sync(0xffffffffu, sel);
    if (sel) {
        int slot = __popc(ball & ((1u << lane) - 1u));
        g_kdst[b * KS + slot] = d;
        g_kw[b * KS + slot]   = score;
        float4 adv = *(const float4*)(g_ad + (tbase + d) * NH);
        float4 ex4;
        float lg;
        lg = as0 + adv.x; lg = lg > 0.f ? lg : 0.2f * lg; ex4.x = expf(lg);
        lg = as1 + adv.y; lg = lg > 0.f ? lg : 0.2f * lg; ex4.y = expf(lg);
        lg = as2 + adv.z; lg = lg > 0.f ? lg : 0.2f * lg; ex4.z = expf(lg);
        lg = as3 + adv.w; lg = lg > 0.f ? lg : 0.2f * lg; ex4.w = expf(lg);
        *(float4*)(g_kex + (b * KS + slot) * NH) = ex4;
        float* ss = g_ssum + (tbase + d) * NH;
        atomicAdd(ss + 0, ex4.x);
        atomicAdd(ss + 1, ex4.y);
        atomicAdd(ss + 2, ex4.z);
        atomicAdd(ss + 3, ex4.w);
    }
}

// ---------------- k4_all: alpha + row-normalize + dedup + out messages (all steps) ----------------
// grid = BS*N/8 blocks, 256 threads (one warp per (t, src)).
__global__ void k4_all(float* __restrict__ outp) {
    int warp = threadIdx.x >> 5, lane = threadIdx.x & 31;
    size_t b = (size_t)blockIdx.x * 8 + warp;   // flat (t*NN + n)
    int n = (int)(b % NN);
    size_t tbase = b - n;                        // t*NN
    const unsigned full = 0xffffffffu;
    int i = (lane >> 2) & 3, h = lane & 3;       // lanes 16..31 mirror 0..15

    int   d_i = g_kdst[b * KS + i];
    float w_i = g_kw[b * KS + i];
    float ex  = g_kex[(b * KS + i) * NH + h];
    float alpha = ex / fmaxf(g_ssum[(tbase + d_i) * NH + h], 1e-16f);

    // row sum over the 4 slots for this head
    float rs = alpha;
    rs += __shfl_xor_sync(full, rs, 4);
    rs += __shfl_xor_sync(full, rs, 8);
    float rinv = 1.f / fmaxf(rs, 1e-9f);

    // dedup: merge duplicate dst into the first slot
    bool first = true;
    float acc = alpha;
#pragma unroll
    for (int jj = 0; jj < KS; jj++) {
        int   dj = __shfl_sync(full, d_i,   jj * 4 + h);
        float aj = __shfl_sync(full, alpha, jj * 4 + h);
        if (jj < i && dj == d_i) first = false;
        if (jj > i && dj == d_i) acc += aj;
    }
    if (lane < 16) {
        g_Aval[(b * KS + i) * NH + h] = first ? acc * rinv : 0.f;
        if (h == 0) g_Adst[b * KS + i] = first ? d_i : -1;
    }

    // out messages: 32 lanes = 4 heads x 8 channels, loop over 4 edges
    int h2 = lane >> 3, c = lane & 7;
    float xhv = g_xh[b * EMB + h2 * CD + c];
#pragma unroll
    for (int jj = 0; jj < KS; jj++) {
        float a_jh = __shfl_sync(full, alpha, jj * 4 + h2);
        float wj   = __shfl_sync(full, w_i,   jj * 4);
        int   dj   = __shfl_sync(full, d_i,   jj * 4);
        atomicAdd(&outp[(tbase + dj) * EMB + h2 * CD + c], a_jh * xhv * wj);
    }
}

// ---------------- scatterA: write the nonzero attention entries ----------------
// one thread per (t,n,slot); each writes its 4 head values.
__global__ void scatterA(float* __restrict__ outp) {
    int gid = blockIdx.x * blockDim.x + threadIdx.x;
    if (gid >= BS * NN * KS) return;
    int slot = gid & 3;
    size_t b = gid >> 2;          // t*NN + n
    int n = (int)(b % NN);
    int t = (int)(b / NN);
    int d = g_Adst[b * KS + slot];
    if (d < 0) return;
    float4 v = *(const float4*)(g_Aval + (b * KS + slot) * NH);
    float* Abase = outp + ATTN_OFS;
    size_t rowstride = (size_t)NN * NN;
    size_t base = ((size_t)t * NH) * rowstride + (size_t)n * NN + d;
    Abase[base]                 = v.x;
    Abase[base + rowstride]     = v.y;
    Abase[base + 2 * rowstride] = v.z;
    Abase[base + 3 * rowstride] = v.w;
}

// ---------------- launch ----------------
extern "C" void kernel_launch(void* const* d_in, const int* in_sizes, int n_in,
                              void* d_out, int out_size) {
    int base = (in_sizes[3] == 1) ? 4 : 3;  // scalar k may or may not be materialized
    const float* Ht  = (const float*)d_in[0];
    const int*   dst = (const int*)d_in[2];
    const float* We1 = (const float*)d_in[base + 0];
    const float* be1 = (const float*)d_in[base + 1];
    const float* We2 = (const float*)d_in[base + 2];
    const float* be2 = (const float*)d_in[base + 3];
    const float* lng = (const float*)d_in[base + 4];
    const float* lnb = (const float*)d_in[base + 5];
    const float* Wih = (const float*)d_in[base + 6];
    const float* Whh = (const float*)d_in[base + 7];
    const float* bih = (const float*)d_in[base + 8];
    const float* bhh = (const float*)d_in[base + 9];
    const float* Ws1 = (const float*)d_in[base + 10];
    const float* bs1 = (const float*)d_in[base + 11];
    const float* Ws2 = (const float*)d_in[base + 12];
    const float* bs2 = (const float*)d_in[base + 13];
    const float* Wgat = (const float*)d_in[base + 14];
    const float* asrc = (const float*)d_in[base + 15];
    const float* adst = (const float*)d_in[base + 16];
    const float* bgat = (const float*)d_in[base + 17];
    float* outp = (float*)d_out;

    embed_k<<<(BS * NN) / RTB, 32>>>(Ht, We1, be1, We2, be2, lng, lnb);
    for (int t = 0; t < BS; t++)
        gru_k<<<NN / GNT, 64>>>(t, Wih, Whh, bih, bhh);
    post_k<<<(BS * NN) / PNT, 64>>>(Ws1, bs1, Wgat, asrc, adst, bgat, outp);
    k2_all<<<(BS * NN) / 8, 256>>>(dst, Ws2, bs2);
    zeroA<<<4608, 256>>>(outp);
    k4_all<<<(BS * NN) / 8, 256>>>(outp);
    scatterA<<<(BS * NN * KS + 255) / 256, 256>>>(outp);
}

// round 5
// speedup vs baseline: 1.5599x; 1.5599x over previous
#include <cuda_runtime.h>
#include <math.h>

// Problem constants (fixed by the reference)
#define NN    1536   // nodes
#define DEG   32     // candidate out-degree per node
#define BS    8      // sequential batch steps
#define OBSD  33
#define HIDN  64
#define NH    4      // heads
#define CD    8      // channels per head
#define KS    4      // top-k
#define EMB   32
#define ATTN_OFS ((size_t)BS * NN * EMB)   // outs precede attns in d_out

#define RTB 8   // rows per block in embed
#define GNT 4   // nodes per block in gru serial step (low reg pressure!)
#define INT 8   // rows per block in gi_all
#define PNT 8   // (t,node) pairs per block in post

// -------- persistent device scratch (no allocations allowed) --------
__device__ float g_Hemb[BS * NN * EMB];
__device__ float g_gi[BS * NN * 3 * HIDN];   // input-side GRU gates (batched)
__device__ float g_h[NN * HIDN];
__device__ float g_hall[BS * NN * HIDN];
__device__ float g_P[BS * NN * HIDN];
__device__ float g_Q[BS * NN * HIDN];
__device__ float g_xh[BS * NN * EMB];
__device__ float g_as[BS * NN * NH];
__device__ float g_ad[BS * NN * NH];
__device__ int   g_kdst[BS * NN * KS];
__device__ float g_kw[BS * NN * KS];
__device__ float g_kex[BS * NN * KS * NH];
__device__ float g_ssum[BS * NN * NH];
__device__ float g_Aval[BS * NN * KS * NH];  // normalized, dedup-merged A entries
__device__ int   g_Adst[BS * NN * KS];       // -1 = duplicate slot (skip)

__device__ __forceinline__ float sigm(float x) { return 1.f / (1.f + expf(-x)); }

// ---------------- zero-fill the whole attention output region ----------------
__global__ void zeroA(float* __restrict__ outp) {
    float4* base = (float4*)(outp + ATTN_OFS);
    size_t total = (size_t)BS * NH * NN * NN / 4;
    size_t stride = (size_t)gridDim.x * blockDim.x;
    float4 z = make_float4(0.f, 0.f, 0.f, 0.f);
    for (size_t i = (size_t)blockIdx.x * blockDim.x + threadIdx.x; i < total; i += stride)
        base[i] = z;
}

// ---------------- Obs embedding: Linear-ReLU-Linear-ReLU-LayerNorm ----------------
// grid = B*N/RTB blocks, 32 threads; each thread computes channel j for RTB rows.
__global__ void __launch_bounds__(32, 16)
embed_k(const float* __restrict__ Ht,
        const float* __restrict__ We1, const float* __restrict__ be1,
        const float* __restrict__ We2, const float* __restrict__ be2,
        const float* __restrict__ lng, const float* __restrict__ lnb) {
    int r0 = blockIdx.x * RTB;
    int j  = threadIdx.x;  // 0..31
    __shared__ float in_s[RTB][OBSD + 1];
    __shared__ float x1_s[RTB][EMB];

    for (int t = j; t < RTB * OBSD; t += 32)
        in_s[t / OBSD][t % OBSD] = Ht[(size_t)r0 * OBSD + t];
    __syncwarp();

    float a[RTB];
    float b1 = be1[j];
#pragma unroll
    for (int m = 0; m < RTB; m++) a[m] = b1;
#pragma unroll
    for (int k = 0; k < OBSD; k++) {
        float w = We1[k * EMB + j];
#pragma unroll
        for (int m = 0; m < RTB; m++) a[m] += in_s[m][k] * w;
    }
#pragma unroll
    for (int m = 0; m < RTB; m++) x1_s[m][j] = fmaxf(a[m], 0.f);
    __syncwarp();

    float b[RTB];
    float b2 = be2[j];
#pragma unroll
    for (int m = 0; m < RTB; m++) b[m] = b2;
#pragma unroll
    for (int k = 0; k < EMB; k++) {
        float w = We2[k * EMB + j];
#pragma unroll
        for (int m = 0; m < RTB; m++) b[m] += x1_s[m][k] * w;
    }

    float gj = lng[j], bj = lnb[j];
#pragma unroll
    for (int m = 0; m < RTB; m++) {
        float x = fmaxf(b[m], 0.f);
        float s = x;
#pragma unroll
        for (int o = 16; o; o >>= 1) s += __shfl_xor_sync(0xffffffffu, s, o);
        float mu = s * (1.f / 32.f);
        float d  = x - mu;
        float v  = d * d;
#pragma unroll
        for (int o = 16; o; o >>= 1) v += __shfl_xor_sync(0xffffffffu, v, o);
        g_Hemb[(size_t)(r0 + m) * EMB + j] = d * rsqrtf(v * (1.f / 32.f) + 1e-5f) * gj + bj;
    }
}

// ---------------- gi_all: input-side GRU gates for ALL steps (batched, parallel) ----------------
// grid = BS*NN/INT blocks, 192 threads; thread j computes gate-output j for INT rows.
__global__ void __launch_bounds__(192, 8)
gi_all(const float* __restrict__ Wih, const float* __restrict__ bih) {
    size_t r0 = (size_t)blockIdx.x * INT;
    int j = threadIdx.x;  // 0..191 -> row of Wih (3H x EMB)
    __shared__ float e_s[INT][EMB];

    for (int t = j; t < INT * EMB; t += 192)
        e_s[t >> 5][t & 31] = g_Hemb[r0 * EMB + t];
    __syncthreads();

    float acc[INT];
    float b = bih[j];
#pragma unroll
    for (int m = 0; m < INT; m++) acc[m] = b;
    const float4* wi = (const float4*)(Wih + (size_t)j * EMB);
#pragma unroll
    for (int k4 = 0; k4 < EMB / 4; k4++) {
        float4 w = wi[k4];
        int k = k4 * 4;
#pragma unroll
        for (int m = 0; m < INT; m++)
            acc[m] += e_s[m][k] * w.x + e_s[m][k + 1] * w.y + e_s[m][k + 2] * w.z + e_s[m][k + 3] * w.w;
    }
#pragma unroll
    for (int m = 0; m < INT; m++)
        g_gi[(r0 + m) * 3 * HIDN + j] = acc[m];
}

// ---------------- GRU serial step: gh = h@Whh^T, combine with precomputed gi ----------------
// grid = NN/GNT blocks, 64 threads; each thread computes output j for GNT nodes.
__global__ void __launch_bounds__(64, 16)
gru_k(int step, const float* __restrict__ Whh, const float* __restrict__ bhh) {
    int n0 = blockIdx.x * GNT;
    int j  = threadIdx.x;  // 0..63
    __shared__ float h_s[GNT][HIDN];

    for (int t = j; t < GNT * HIDN; t += 64)
        h_s[t >> 6][t & 63] = (step == 0) ? 0.f : g_h[(size_t)n0 * HIDN + t];
    __syncthreads();

    float ah0[GNT], ah1[GNT], ah2[GNT];
    {
        float b0 = bhh[j], b1 = bhh[HIDN + j], b2 = bhh[2 * HIDN + j];
#pragma unroll
        for (int m = 0; m < GNT; m++) { ah0[m] = b0; ah1[m] = b1; ah2[m] = b2; }
    }
    const float4* w0 = (const float4*)(Whh + (size_t)j * HIDN);
    const float4* w1 = (const float4*)(Whh + (size_t)(HIDN + j) * HIDN);
    const float4* w2 = (const float4*)(Whh + (size_t)(2 * HIDN + j) * HIDN);
#pragma unroll
    for (int k4 = 0; k4 < HIDN / 4; k4++) {
        float4 a = w0[k4], b = w1[k4], c = w2[k4];
        int k = k4 * 4;
#pragma unroll
        for (int m = 0; m < GNT; m++) {
            float e0 = h_s[m][k], e1 = h_s[m][k + 1], e2 = h_s[m][k + 2], e3 = h_s[m][k + 3];
            ah0[m] += e0 * a.x + e1 * a.y + e2 * a.z + e3 * a.w;
            ah1[m] += e0 * b.x + e1 * b.y + e2 * b.z + e3 * b.w;
            ah2[m] += e0 * c.x + e1 * c.y + e2 * c.z + e3 * c.w;
        }
    }
#pragma unroll
    for (int m = 0; m < GNT; m++) {
        size_t b = (size_t)step * NN + n0 + m;
        const float* gi = g_gi + b * 3 * HIDN;
        float r  = sigm(gi[j] + ah0[m]);
        float z  = sigm(gi[HIDN + j] + ah1[m]);
        float nv = tanhf(gi[2 * HIDN + j] + r * ah2[m]);
        float hn = (1.f - z) * nv + z * h_s[m][j];
        g_h[(size_t)(n0 + m) * HIDN + j] = hn;
        g_hall[b * HIDN + j] = hn;
    }
}

// ---------------- post_all: P/Q/xh/a_s/a_d + inits for ALL steps at once ----------------
// grid = BS*N/PNT blocks, 64 threads.
__global__ void __launch_bounds__(64, 16)
post_k(const float* __restrict__ Ws1, const float* __restrict__ bs1,
       const float* __restrict__ Wgat,
       const float* __restrict__ asrc, const float* __restrict__ adst,
       const float* __restrict__ bgat,
       float* __restrict__ outp) {
    size_t r0 = (size_t)blockIdx.x * PNT;   // flat (t*NN+n) index
    int j = threadIdx.x;                    // 0..63
    __shared__ float hn_s[PNT][HIDN];
    __shared__ float xh_s[PNT][EMB];

    for (int t = j; t < PNT * HIDN; t += 64)
        hn_s[t >> 6][t & 63] = g_hall[r0 * HIDN + t];
    __syncthreads();

    float p[PNT], q[PNT];
    float bp = bs1[j];
#pragma unroll
    for (int m = 0; m < PNT; m++) { p[m] = bp; q[m] = 0.f; }
#pragma unroll 8
    for (int k = 0; k < HIDN; k++) {
        float w1 = Ws1[k * HIDN + j];
        float w2 = Ws1[(HIDN + k) * HIDN + j];
#pragma unroll
        for (int m = 0; m < PNT; m++) { p[m] += hn_s[m][k] * w1; q[m] += hn_s[m][k] * w2; }
    }
#pragma unroll
    for (int m = 0; m < PNT; m++) {
        g_P[(r0 + m) * HIDN + j] = p[m];
        g_Q[(r0 + m) * HIDN + j] = q[m];
    }

    if (j < EMB) {
        float x[PNT];
#pragma unroll
        for (int m = 0; m < PNT; m++) x[m] = 0.f;
#pragma unroll 8
        for (int k = 0; k < HIDN; k++) {
            float w = Wgat[k * EMB + j];
#pragma unroll
            for (int m = 0; m < PNT; m++) x[m] += hn_s[m][k] * w;
        }
        float bg = bgat[j];
#pragma unroll
        for (int m = 0; m < PNT; m++) {
            xh_s[m][j] = x[m];
            g_xh[(r0 + m) * EMB + j] = x[m];
            outp[(r0 + m) * EMB + j] = bg;  // segment_sum init + bias
        }
    }
    __syncthreads();

    if (j < PNT * NH) {
        int m = j >> 2, h = j & 3;
        float as_ = 0.f, ad_ = 0.f;
#pragma unroll
        for (int c = 0; c < CD; c++) {
            as_ += xh_s[m][h * CD + c] * asrc[h * CD + c];
            ad_ += xh_s[m][h * CD + c] * adst[h * CD + c];
        }
        g_as[(r0 + m) * NH + h]   = as_;
        g_ad[(r0 + m) * NH + h]   = ad_;
        g_ssum[(r0 + m) * NH + h] = 0.f;
    }
}

// ---------------- k2_all: edge scores + warp top-k + exp + segment sums (all steps) ----------------
// grid = BS*N/8 blocks, 256 threads (one warp per (t, src)).
__global__ void __launch_bounds__(256, 8)
k2_all(const int* __restrict__ dst,
       const float* __restrict__ Ws2, const float* __restrict__ bs2) {
    int warp = threadIdx.x >> 5, lane = threadIdx.x & 31;
    size_t b = (size_t)blockIdx.x * 8 + warp;   // flat (t*NN + n)
    int n = (int)(b % NN);
    size_t tbase = b - n;                        // t*NN

    __shared__ float w2_s[HIDN];
    __shared__ float P_sh[8][HIDN];
    if (threadIdx.x < HIDN) w2_s[threadIdx.x] = Ws2[threadIdx.x];
    P_sh[warp][lane]      = g_P[b * HIDN + lane];
    P_sh[warp][32 + lane] = g_P[b * HIDN + 32 + lane];
    float as0 = g_as[b * NH + 0], as1 = g_as[b * NH + 1];
    float as2 = g_as[b * NH + 2], as3 = g_as[b * NH + 3];
    __syncthreads();

    int d = dst[n * DEG + lane];
    const float4* Qr = (const float4*)(g_Q + (tbase + d) * HIDN);
    float acc = bs2[0];
    const float* P_s = P_sh[warp];
#pragma unroll
    for (int k4 = 0; k4 < HIDN / 4; k4++) {
        float4 qv = Qr[k4];
        int k = k4 * 4;
        acc += fmaxf(P_s[k] + qv.x, 0.f) * w2_s[k]
             + fmaxf(P_s[k + 1] + qv.y, 0.f) * w2_s[k + 1]
             + fmaxf(P_s[k + 2] + qv.z, 0.f) * w2_s[k + 2]
             + fmaxf(P_s[k + 3] + qv.w, 0.f) * w2_s[k + 3];
    }
    float score = sigm(acc);

    // top-k (k=4) among 32 lanes; ties -> lower index (matches jax.lax.top_k)
    bool sel = false;
#pragma unroll
    for (int r = 0; r < KS; r++) {
        float v = sel ? -1e30f : score;
        int   idx = lane;
#pragma unroll
        for (int o = 16; o; o >>= 1) {
            float ov = __shfl_xor_sync(0xffffffffu, v, o);
            int   oi = __shfl_xor_sync(0xffffffffu, idx, o);
            if (ov > v || (ov == v && oi < idx)) { v = ov; idx = oi; }
        }
        if (lane == idx) sel = true;
    }
    unsigned ball = __ballot_sync(0xffffffffu, sel);
    if (sel) {
        int slot = __popc(ball & ((1u << lane) - 1u));
        g_kdst[b * KS + slot] = d;
        g_kw[b * KS + slot]   = score;
        float4 adv = *(const float4*)(g_ad + (tbase + d) * NH);
        float4 ex4;
        float lg;
        lg = as0 + adv.x; lg = lg > 0.f ? lg : 0.2f * lg; ex4.x = expf(lg);
        lg = as1 + adv.y; lg = lg > 0.f ? lg : 0.2f * lg; ex4.y = expf(lg);
        lg = as2 + adv.z; lg = lg > 0.f ? lg : 0.2f * lg; ex4.z = expf(lg);
        lg = as3 + adv.w; lg = lg > 0.f ? lg : 0.2f * lg; ex4.w = expf(lg);
        *(float4*)(g_kex + (b * KS + slot) * NH) = ex4;
        float* ss = g_ssum + (tbase + d) * NH;
        atomicAdd(ss + 0, ex4.x);
        atomicAdd(ss + 1, ex4.y);
        atomicAdd(ss + 2, ex4.z);
        atomicAdd(ss + 3, ex4.w);
    }
}

// ---------------- k4_all: alpha + row-normalize + dedup + out messages (all steps) ----------------
// grid = BS*N/8 blocks, 256 threads (one warp per (t, src)).
__global__ void __launch_bounds__(256, 8)
k4_all(float* __restrict__ outp) {
    int warp = threadIdx.x >> 5, lane = threadIdx.x & 31;
    size_t b = (size_t)blockIdx.x * 8 + warp;   // flat (t*NN + n)
    int n = (int)(b % NN);
    size_t tbase = b - n;                        // t*NN
    const unsigned full = 0xffffffffu;
    int i = (lane >> 2) & 3, h = lane & 3;       // lanes 16..31 mirror 0..15

    int   d_i = g_kdst[b * KS + i];
    float w_i = g_kw[b * KS + i];
    float ex  = g_kex[(b * KS + i) * NH + h];
    float alpha = ex / fmaxf(g_ssum[(tbase + d_i) * NH + h], 1e-16f);

    // row sum over the 4 slots for this head
    float rs = alpha;
    rs += __shfl_xor_sync(full, rs, 4);
    rs += __shfl_xor_sync(full, rs, 8);
    float rinv = 1.f / fmaxf(rs, 1e-9f);

    // dedup: merge duplicate dst into the first slot
    bool first = true;
    float acc = alpha;
#pragma unroll
    for (int jj = 0; jj < KS; jj++) {
        int   dj = __shfl_sync(full, d_i,   jj * 4 + h);
        float aj = __shfl_sync(full, alpha, jj * 4 + h);
        if (jj < i && dj == d_i) first = false;
        if (jj > i && dj == d_i) acc += aj;
    }
    if (lane < 16) {
        g_Aval[(b * KS + i) * NH + h] = first ? acc * rinv : 0.f;
        if (h == 0) g_Adst[b * KS + i] = first ? d_i : -1;
    }

    // out messages: 32 lanes = 4 heads x 8 channels, loop over 4 edges
    int h2 = lane >> 3, c = lane & 7;
    float xhv = g_xh[b * EMB + h2 * CD + c];
#pragma unroll
    for (int jj = 0; jj < KS; jj++) {
        float a_jh = __shfl_sync(full, alpha, jj * 4 + h2);
        float wj   = __shfl_sync(full, w_i,   jj * 4);
        int   dj   = __shfl_sync(full, d_i,   jj * 4);
        atomicAdd(&outp[(tbase + dj) * EMB + h2 * CD + c], a_jh * xhv * wj);
    }
}

// ---------------- scatterA: write the nonzero attention entries ----------------
// one thread per (t,n,slot); each writes its 4 head values.
__global__ void scatterA(float* __restrict__ outp) {
    int gid = blockIdx.x * blockDim.x + threadIdx.x;
    if (gid >= BS * NN * KS) return;
    int slot = gid & 3;
    size_t b = gid >> 2;          // t*NN + n
    int n = (int)(b % NN);
    int t = (int)(b / NN);
    int d = g_Adst[b * KS + slot];
    if (d < 0) return;
    float4 v = *(const float4*)(g_Aval + (b * KS + slot) * NH);
    float* Abase = outp + ATTN_OFS;
    size_t rowstride = (size_t)NN * NN;
    size_t base = ((size_t)t * NH) * rowstride + (size_t)n * NN + d;
    Abase[base]                 = v.x;
    Abase[base + rowstride]     = v.y;
    Abase[base + 2 * rowstride] = v.z;
    Abase[base + 3 * rowstride] = v.w;
}

// ---------------- launch ----------------
extern "C" void kernel_launch(void* const* d_in, const int* in_sizes, int n_in,
                              void* d_out, int out_size) {
    int base = (in_sizes[3] == 1) ? 4 : 3;  // scalar k may or may not be materialized
    const float* Ht  = (const float*)d_in[0];
    const int*   dst = (const int*)d_in[2];
    const float* We1 = (const float*)d_in[base + 0];
    const float* be1 = (const float*)d_in[base + 1];
    const float* We2 = (const float*)d_in[base + 2];
    const float* be2 = (const float*)d_in[base + 3];
    const float* lng = (const float*)d_in[base + 4];
    const float* lnb = (const float*)d_in[base + 5];
    const float* Wih = (const float*)d_in[base + 6];
    const float* Whh = (const float*)d_in[base + 7];
    const float* bih = (const float*)d_in[base + 8];
    const float* bhh = (const float*)d_in[base + 9];
    const float* Ws1 = (const float*)d_in[base + 10];
    const float* bs1 = (const float*)d_in[base + 11];
    const float* Ws2 = (const float*)d_in[base + 12];
    const float* bs2 = (const float*)d_in[base + 13];
    const float* Wgat = (const float*)d_in[base + 14];
    const float* asrc = (const float*)d_in[base + 15];
    const float* adst = (const float*)d_in[base + 16];
    const float* bgat = (const float*)d_in[base + 17];
    float* outp = (float*)d_out;

    embed_k<<<(BS * NN) / RTB, 32>>>(Ht, We1, be1, We2, be2, lng, lnb);
    gi_all<<<(BS * NN) / INT, 192>>>(Wih, bih);
    for (int t = 0; t < BS; t++)
        gru_k<<<NN / GNT, 64>>>(t, Whh, bhh);
    post_k<<<(BS * NN) / PNT, 64>>>(Ws1, bs1, Wgat, asrc, adst, bgat, outp);
    k2_all<<<(BS * NN) / 8, 256>>>(dst, Ws2, bs2);
    zeroA<<<4608, 256>>>(outp);
    k4_all<<<(BS * NN) / 8, 256>>>(outp);
    scatterA<<<(BS * NN * KS + 255) / 256, 256>>>(outp);
}

// round 6
// speedup vs baseline: 2.0740x; 1.3296x over previous
#include <cuda_runtime.h>
#include <math.h>

// Problem constants (fixed by the reference)
#define NN    1536   // nodes
#define DEG   32     // candidate out-degree per node
#define BS    8      // sequential batch steps
#define OBSD  33
#define HIDN  64
#define NH    4      // heads
#define CD    8      // channels per head
#define KS    4      // top-k
#define EMB   32
#define ATTN_OFS ((size_t)BS * NN * EMB)   // outs precede attns in d_out

#define RTB 8    // rows per block in embed
#define INT 8    // rows per block in gi_all
#define PNT 8    // (t,node) pairs per block in post
#define GN  8    // nodes per block in gruAll

// shared layout for gruAll (floats): W[192*68] | b[192] | h[GN*68] | gi[GN*196]
#define W_STR 68
#define H_STR 68
#define GI_STR 196
#define SM_W  0
#define SM_B  (192 * W_STR)
#define SM_H  (SM_B + 192)
#define SM_GI (SM_H + GN * H_STR)
#define SM_TOT (SM_GI + GN * GI_STR)          // 15360 floats = 61440 bytes

// -------- persistent device scratch (no allocations allowed) --------
__device__ float g_Hemb[BS * NN * EMB];
__device__ float g_gi[BS * NN * 3 * HIDN];   // input-side GRU gates (batched)
__device__ float g_hall[BS * NN * HIDN];
__device__ float g_P[BS * NN * HIDN];
__device__ float g_Q[BS * NN * HIDN];
__device__ float g_xh[BS * NN * EMB];
__device__ float g_as[BS * NN * NH];
__device__ float g_ad[BS * NN * NH];
__device__ int   g_kdst[BS * NN * KS];
__device__ float g_kw[BS * NN * KS];
__device__ float g_kex[BS * NN * KS * NH];
__device__ float g_ssum[BS * NN * NH];
__device__ float g_Aval[BS * NN * KS * NH];  // normalized, dedup-merged A entries
__device__ int   g_Adst[BS * NN * KS];       // -1 = duplicate slot (skip)

__device__ __forceinline__ float sigm(float x) { return 1.f / (1.f + expf(-x)); }

// ---------------- zero-fill the whole attention output region ----------------
__global__ void zeroA(float* __restrict__ outp) {
    float4* base = (float4*)(outp + ATTN_OFS);
    size_t total = (size_t)BS * NH * NN * NN / 4;
    size_t stride = (size_t)gridDim.x * blockDim.x;
    float4 z = make_float4(0.f, 0.f, 0.f, 0.f);
    for (size_t i = (size_t)blockIdx.x * blockDim.x + threadIdx.x; i < total; i += stride)
        base[i] = z;
}

// ---------------- Obs embedding: Linear-ReLU-Linear-ReLU-LayerNorm ----------------
__global__ void __launch_bounds__(32, 16)
embed_k(const float* __restrict__ Ht,
        const float* __restrict__ We1, const float* __restrict__ be1,
        const float* __restrict__ We2, const float* __restrict__ be2,
        const float* __restrict__ lng, const float* __restrict__ lnb) {
    int r0 = blockIdx.x * RTB;
    int j  = threadIdx.x;  // 0..31
    __shared__ float in_s[RTB][OBSD + 1];
    __shared__ float x1_s[RTB][EMB];

    for (int t = j; t < RTB * OBSD; t += 32)
        in_s[t / OBSD][t % OBSD] = Ht[(size_t)r0 * OBSD + t];
    __syncwarp();

    float a[RTB];
    float b1 = be1[j];
#pragma unroll
    for (int m = 0; m < RTB; m++) a[m] = b1;
#pragma unroll
    for (int k = 0; k < OBSD; k++) {
        float w = We1[k * EMB + j];
#pragma unroll
        for (int m = 0; m < RTB; m++) a[m] += in_s[m][k] * w;
    }
#pragma unroll
    for (int m = 0; m < RTB; m++) x1_s[m][j] = fmaxf(a[m], 0.f);
    __syncwarp();

    float b[RTB];
    float b2 = be2[j];
#pragma unroll
    for (int m = 0; m < RTB; m++) b[m] = b2;
#pragma unroll
    for (int k = 0; k < EMB; k++) {
        float w = We2[k * EMB + j];
#pragma unroll
        for (int m = 0; m < RTB; m++) b[m] += x1_s[m][k] * w;
    }

    float gj = lng[j], bj = lnb[j];
#pragma unroll
    for (int m = 0; m < RTB; m++) {
        float x = fmaxf(b[m], 0.f);
        float s = x;
#pragma unroll
        for (int o = 16; o; o >>= 1) s += __shfl_xor_sync(0xffffffffu, s, o);
        float mu = s * (1.f / 32.f);
        float d  = x - mu;
        float v  = d * d;
#pragma unroll
        for (int o = 16; o; o >>= 1) v += __shfl_xor_sync(0xffffffffu, v, o);
        g_Hemb[(size_t)(r0 + m) * EMB + j] = d * rsqrtf(v * (1.f / 32.f) + 1e-5f) * gj + bj;
    }
}

// ---------------- gi_all: input-side GRU gates for ALL steps (batched) ----------------
__global__ void __launch_bounds__(192, 8)
gi_all(const float* __restrict__ Wih, const float* __restrict__ bih) {
    size_t r0 = (size_t)blockIdx.x * INT;
    int j = threadIdx.x;  // 0..191 -> row of Wih (3H x EMB)
    __shared__ float e_s[INT][EMB];

    for (int t = j; t < INT * EMB; t += 192)
        e_s[t >> 5][t & 31] = g_Hemb[r0 * EMB + t];
    __syncthreads();

    float acc[INT];
    float b = bih[j];
#pragma unroll
    for (int m = 0; m < INT; m++) acc[m] = b;
    const float4* wi = (const float4*)(Wih + (size_t)j * EMB);
#pragma unroll
    for (int k4 = 0; k4 < EMB / 4; k4++) {
        float4 w = wi[k4];
        int k = k4 * 4;
#pragma unroll
        for (int m = 0; m < INT; m++)
            acc[m] += e_s[m][k] * w.x + e_s[m][k + 1] * w.y + e_s[m][k + 2] * w.z + e_s[m][k + 3] * w.w;
    }
#pragma unroll
    for (int m = 0; m < INT; m++)
        g_gi[(r0 + m) * 3 * HIDN + j] = acc[m];
}

// ---------------- gruAll: ALL 8 GRU steps in ONE launch (per-node recurrence) ----------------
// grid = NN/GN = 192 blocks, 256 threads. Thread (w=tid>>5, lane=tid&31):
//   node m = lane & 7, j-quarter jq = lane >> 3; thread owns j = w*8 + jq*2 + {0,1}.
// Whh staged in shared (row stride 68: bank-safe, float4-aligned); h lives in shared across steps.
__global__ void __launch_bounds__(256, 2)
gruAll(const float* __restrict__ Whh, const float* __restrict__ bhh) {
    extern __shared__ float sm[];
    float* W_s  = sm + SM_W;
    float* b_s  = sm + SM_B;
    float* h_s  = sm + SM_H;
    float* gi_s = sm + SM_GI;

    int n0  = blockIdx.x * GN;
    int tid = threadIdx.x;
    int lane = tid & 31, w = tid >> 5;
    int m  = lane & 7;            // node within block
    int jb = w * 8 + (lane >> 3) * 2;  // j base; thread covers jb, jb+1

    // stage weights (row-major, padded stride) + biases, zero h
    for (int i = tid; i < 192 * HIDN; i += 256)
        W_s[(i >> 6) * W_STR + (i & 63)] = Whh[i];
    for (int i = tid; i < 192; i += 256) b_s[i] = bhh[i];
    for (int i = tid; i < GN * H_STR; i += 256) h_s[i] = 0.f;
    __syncthreads();

    for (int t = 0; t < BS; t++) {
        // stage gi for this step
        size_t gbase = ((size_t)t * NN + n0) * 192;
        for (int i = tid; i < GN * 192; i += 256)
            gi_s[(i / 192) * GI_STR + (i % 192)] = g_gi[gbase + i];
        __syncthreads();

        // gh = h[m] @ Whh^T for this thread's two j's, three gates
        float a0[2] = {0.f, 0.f}, a1[2] = {0.f, 0.f}, a2[2] = {0.f, 0.f};
        const float* hrow = h_s + m * H_STR;
#pragma unroll
        for (int k4 = 0; k4 < HIDN / 4; k4++) {
            float4 h4 = *(const float4*)(hrow + k4 * 4);
#pragma unroll
            for (int u = 0; u < 2; u++) {
                int j = jb + u;
                float4 w0 = *(const float4*)(W_s + j * W_STR + k4 * 4);
                float4 w1 = *(const float4*)(W_s + (64 + j) * W_STR + k4 * 4);
                float4 w2 = *(const float4*)(W_s + (128 + j) * W_STR + k4 * 4);
                a0[u] += h4.x * w0.x + h4.y * w0.y + h4.z * w0.z + h4.w * w0.w;
                a1[u] += h4.x * w1.x + h4.y * w1.y + h4.z * w1.z + h4.w * w1.w;
                a2[u] += h4.x * w2.x + h4.y * w2.y + h4.z * w2.z + h4.w * w2.w;
            }
        }

        // activation (read old h before the write barrier)
        float hnv[2];
#pragma unroll
        for (int u = 0; u < 2; u++) {
            int j = jb + u;
            float r  = sigm(gi_s[m * GI_STR + j]       + a0[u] + b_s[j]);
            float z  = sigm(gi_s[m * GI_STR + 64 + j]  + a1[u] + b_s[64 + j]);
            float nv = tanhf(gi_s[m * GI_STR + 128 + j] + (a2[u] + b_s[128 + j]) * r);
            hnv[u] = (1.f - z) * nv + z * hrow[j];
        }
        __syncthreads();   // all reads of old h done
#pragma unroll
        for (int u = 0; u < 2; u++) h_s[m * H_STR + jb + u] = hnv[u];
        __syncthreads();   // new h visible

        // write h for this step (coalesced)
        for (int i = tid; i < GN * HIDN; i += 256)
            g_hall[((size_t)t * NN + n0 + (i >> 6)) * HIDN + (i & 63)] = h_s[(i >> 6) * H_STR + (i & 63)];
        __syncthreads();   // keep gi_s stable until all reads done (next stage overwrites)
    }
}

// ---------------- post_all: P/Q/xh/a_s/a_d + inits for ALL steps at once ----------------
__global__ void __launch_bounds__(64, 16)
post_k(const float* __restrict__ Ws1, const float* __restrict__ bs1,
       const float* __restrict__ Wgat,
       const float* __restrict__ asrc, const float* __restrict__ adst,
       const float* __restrict__ bgat,
       float* __restrict__ outp) {
    size_t r0 = (size_t)blockIdx.x * PNT;   // flat (t*NN+n) index
    int j = threadIdx.x;                    // 0..63
    __shared__ float hn_s[PNT][HIDN];
    __shared__ float xh_s[PNT][EMB];

    for (int t = j; t < PNT * HIDN; t += 64)
        hn_s[t >> 6][t & 63] = g_hall[r0 * HIDN + t];
    __syncthreads();

    float p[PNT], q[PNT];
    float bp = bs1[j];
#pragma unroll
    for (int m = 0; m < PNT; m++) { p[m] = bp; q[m] = 0.f; }
#pragma unroll 8
    for (int k = 0; k < HIDN; k++) {
        float w1 = Ws1[k * HIDN + j];
        float w2 = Ws1[(HIDN + k) * HIDN + j];
#pragma unroll
        for (int m = 0; m < PNT; m++) { p[m] += hn_s[m][k] * w1; q[m] += hn_s[m][k] * w2; }
    }
#pragma unroll
    for (int m = 0; m < PNT; m++) {
        g_P[(r0 + m) * HIDN + j] = p[m];
        g_Q[(r0 + m) * HIDN + j] = q[m];
    }

    if (j < EMB) {
        float x[PNT];
#pragma unroll
        for (int m = 0; m < PNT; m++) x[m] = 0.f;
#pragma unroll 8
        for (int k = 0; k < HIDN; k++) {
            float w = Wgat[k * EMB + j];
#pragma unroll
            for (int m = 0; m < PNT; m++) x[m] += hn_s[m][k] * w;
        }
        float bg = bgat[j];
#pragma unroll
        for (int m = 0; m < PNT; m++) {
            xh_s[m][j] = x[m];
            g_xh[(r0 + m) * EMB + j] = x[m];
            outp[(r0 + m) * EMB + j] = bg;  // segment_sum init + bias
        }
    }
    __syncthreads();

    if (j < PNT * NH) {
        int m = j >> 2, h = j & 3;
        float as_ = 0.f, ad_ = 0.f;
#pragma unroll
        for (int c = 0; c < CD; c++) {
            as_ += xh_s[m][h * CD + c] * asrc[h * CD + c];
            ad_ += xh_s[m][h * CD + c] * adst[h * CD + c];
        }
        g_as[(r0 + m) * NH + h]   = as_;
        g_ad[(r0 + m) * NH + h]   = ad_;
        g_ssum[(r0 + m) * NH + h] = 0.f;
    }
}

// ---------------- k2_all: edge scores + warp top-k + exp + segment sums ----------------
__global__ void __launch_bounds__(256, 8)
k2_all(const int* __restrict__ dst,
       const float* __restrict__ Ws2, const float* __restrict__ bs2) {
    int warp = threadIdx.x >> 5, lane = threadIdx.x & 31;
    size_t b = (size_t)blockIdx.x * 8 + warp;   // flat (t*NN + n)
    int n = (int)(b % NN);
    size_t tbase = b - n;                        // t*NN

    __shared__ float w2_s[HIDN];
    __shared__ float P_sh[8][HIDN];
    if (threadIdx.x < HIDN) w2_s[threadIdx.x] = Ws2[threadIdx.x];
    P_sh[warp][lane]      = g_P[b * HIDN + lane];
    P_sh[warp][32 + lane] = g_P[b * HIDN + 32 + lane];
    float as0 = g_as[b * NH + 0], as1 = g_as[b * NH + 1];
    float as2 = g_as[b * NH + 2], as3 = g_as[b * NH + 3];
    __syncthreads();

    int d = dst[n * DEG + lane];
    const float4* Qr = (const float4*)(g_Q + (tbase + d) * HIDN);
    float acc = bs2[0];
    const float* P_s = P_sh[warp];
#pragma unroll
    for (int k4 = 0; k4 < HIDN / 4; k4++) {
        float4 qv = Qr[k4];
        int k = k4 * 4;
        acc += fmaxf(P_s[k] + qv.x, 0.f) * w2_s[k]
             + fmaxf(P_s[k + 1] + qv.y, 0.f) * w2_s[k + 1]
             + fmaxf(P_s[k + 2] + qv.z, 0.f) * w2_s[k + 2]
             + fmaxf(P_s[k + 3] + qv.w, 0.f) * w2_s[k + 3];
    }
    float score = sigm(acc);

    // top-k (k=4) among 32 lanes; ties -> lower index (matches jax.lax.top_k)
    bool sel = false;
#pragma unroll
    for (int r = 0; r < KS; r++) {
        float v = sel ? -1e30f : score;
        int   idx = lane;
#pragma unroll
        for (int o = 16; o; o >>= 1) {
            float ov = __shfl_xor_sync(0xffffffffu, v, o);
            int   oi = __shfl_xor_sync(0xffffffffu, idx, o);
            if (ov > v || (ov == v && oi < idx)) { v = ov; idx = oi; }
        }
        if (lane == idx) sel = true;
    }
    unsigned ball = __ballot_sync(0xffffffffu, sel);
    if (sel) {
        int slot = __popc(ball & ((1u << lane) - 1u));
        g_kdst[b * KS + slot] = d;
        g_kw[b * KS + slot]   = score;
        float4 adv = *(const float4*)(g_ad + (tbase + d) * NH);
        float4 ex4;
        float lg;
        lg = as0 + adv.x; lg = lg > 0.f ? lg : 0.2f * lg; ex4.x = expf(lg);
        lg = as1 + adv.y; lg = lg > 0.f ? lg : 0.2f * lg; ex4.y = expf(lg);
        lg = as2 + adv.z; lg = lg > 0.f ? lg : 0.2f * lg; ex4.z = expf(lg);
        lg = as3 + adv.w; lg = lg > 0.f ? lg : 0.2f * lg; ex4.w = expf(lg);
        *(float4*)(g_kex + (b * KS + slot) * NH) = ex4;
        float* ss = g_ssum + (tbase + d) * NH;
        atomicAdd(ss + 0, ex4.x);
        atomicAdd(ss + 1, ex4.y);
        atomicAdd(ss + 2, ex4.z);
        atomicAdd(ss + 3, ex4.w);
    }
}

// ---------------- k4_all: alpha + row-normalize + dedup + out messages ----------------
__global__ void __launch_bounds__(256, 8)
k4_all(float* __restrict__ outp) {
    int warp = threadIdx.x >> 5, lane = threadIdx.x & 31;
    size_t b = (size_t)blockIdx.x * 8 + warp;   // flat (t*NN + n)
    int n = (int)(b % NN);
    size_t tbase = b - n;                        // t*NN
    const unsigned full = 0xffffffffu;
    int i = (lane >> 2) & 3, h = lane & 3;       // lanes 16..31 mirror 0..15

    int   d_i = g_kdst[b * KS + i];
    float w_i = g_kw[b * KS + i];
    float ex  = g_kex[(b * KS + i) * NH + h];
    float alpha = ex / fmaxf(g_ssum[(tbase + d_i) * NH + h], 1e-16f);

    // row sum over the 4 slots for this head
    float rs = alpha;
    rs += __shfl_xor_sync(full, rs, 4);
    rs += __shfl_xor_sync(full, rs, 8);
    float rinv = 1.f / fmaxf(rs, 1e-9f);

    // dedup: merge duplicate dst into the first slot
    bool first = true;
    float acc = alpha;
#pragma unroll
    for (int jj = 0; jj < KS; jj++) {
        int   dj = __shfl_sync(full, d_i,   jj * 4 + h);
        float aj = __shfl_sync(full, alpha, jj * 4 + h);
        if (jj < i && dj == d_i) first = false;
        if (jj > i && dj == d_i) acc += aj;
    }
    if (lane < 16) {
        g_Aval[(b * KS + i) * NH + h] = first ? acc * rinv : 0.f;
        if (h == 0) g_Adst[b * KS + i] = first ? d_i : -1;
    }

    // out messages: 32 lanes = 4 heads x 8 channels, loop over 4 edges
    int h2 = lane >> 3, c = lane & 7;
    float xhv = g_xh[b * EMB + h2 * CD + c];
#pragma unroll
    for (int jj = 0; jj < KS; jj++) {
        float a_jh = __shfl_sync(full, alpha, jj * 4 + h2);
        float wj   = __shfl_sync(full, w_i,   jj * 4);
        int   dj   = __shfl_sync(full, d_i,   jj * 4);
        atomicAdd(&outp[(tbase + dj) * EMB + h2 * CD + c], a_jh * xhv * wj);
    }
}

// ---------------- scatterA: write the nonzero attention entries ----------------
__global__ void scatterA(float* __restrict__ outp) {
    int gid = blockIdx.x * blockDim.x + threadIdx.x;
    if (gid >= BS * NN * KS) return;
    int slot = gid & 3;
    size_t b = gid >> 2;          // t*NN + n
    int n = (int)(b % NN);
    int t = (int)(b / NN);
    int d = g_Adst[b * KS + slot];
    if (d < 0) return;
    float4 v = *(const float4*)(g_Aval + (b * KS + slot) * NH);
    float* Abase = outp + ATTN_OFS;
    size_t rowstride = (size_t)NN * NN;
    size_t base = ((size_t)t * NH) * rowstride + (size_t)n * NN + d;
    Abase[base]                 = v.x;
    Abase[base + rowstride]     = v.y;
    Abase[base + 2 * rowstride] = v.z;
    Abase[base + 3 * rowstride] = v.w;
}

// ---------------- launch ----------------
extern "C" void kernel_launch(void* const* d_in, const int* in_sizes, int n_in,
                              void* d_out, int out_size) {
    int base = (in_sizes[3] == 1) ? 4 : 3;  // scalar k may or may not be materialized
    const float* Ht  = (const float*)d_in[0];
    const int*   dst = (const int*)d_in[2];
    const float* We1 = (const float*)d_in[base + 0];
    const float* be1 = (const float*)d_in[base + 1];
    const float* We2 = (const float*)d_in[base + 2];
    const float* be2 = (const float*)d_in[base + 3];
    const float* lng = (const float*)d_in[base + 4];
    const float* lnb = (const float*)d_in[base + 5];
    const float* Wih = (const float*)d_in[base + 6];
    const float* Whh = (const float*)d_in[base + 7];
    const float* bih = (const float*)d_in[base + 8];
    const float* bhh = (const float*)d_in[base + 9];
    const float* Ws1 = (const float*)d_in[base + 10];
    const float* bs1 = (const float*)d_in[base + 11];
    const float* Ws2 = (const float*)d_in[base + 12];
    const float* bs2 = (const float*)d_in[base + 13];
    const float* Wgat = (const float*)d_in[base + 14];
    const float* asrc = (const float*)d_in[base + 15];
    const float* adst = (const float*)d_in[base + 16];
    const float* bgat = (const float*)d_in[base + 17];
    float* outp = (float*)d_out;

    static int smem_set = 0;
    (void)smem_set;
    cudaFuncSetAttribute(gruAll, cudaFuncAttributeMaxDynamicSharedMemorySize, SM_TOT * 4);

    embed_k<<<(BS * NN) / RTB, 32>>>(Ht, We1, be1, We2, be2, lng, lnb);
    gi_all<<<(BS * NN) / INT, 192>>>(Wih, bih);
    gruAll<<<NN / GN, 256, SM_TOT * 4>>>(Whh, bhh);
    post_k<<<(BS * NN) / PNT, 64>>>(Ws1, bs1, Wgat, asrc, adst, bgat, outp);
    k2_all<<<(BS * NN) / 8, 256>>>(dst, Ws2, bs2);
    zeroA<<<4608, 256>>>(outp);
    k4_all<<<(BS * NN) / 8, 256>>>(outp);
    scatterA<<<(BS * NN * KS + 255) / 256, 256>>>(outp);
}

// round 7
// speedup vs baseline: 2.0782x; 1.0020x over previous
#include <cuda_runtime.h>
#include <math.h>

// Problem constants (fixed by the reference)
#define NN    1536   // nodes
#define DEG   32     // candidate out-degree per node
#define BS    8      // sequential batch steps
#define OBSD  33
#define HIDN  64
#define NH    4      // heads
#define CD    8      // channels per head
#define KS    4      // top-k
#define EMB   32
#define ATTN_OFS ((size_t)BS * NN * EMB)   // outs precede attns in d_out

#define RTB 8    // rows per block in embed
#define INT 8    // rows per block in gi_all
#define PNT 32   // (t,node) pairs per block in post (4 groups x 8)
#define GN  8    // nodes per block in gruAll

// shared layout for gruAll (floats): W[192*68] | b[192] | h[GN*68] | gi[GN*196]
#define W_STR 68
#define H_STR 68
#define GI_STR 196
#define SM_W  0
#define SM_B  (192 * W_STR)
#define SM_H  (SM_B + 192)
#define SM_GI (SM_H + GN * H_STR)
#define SM_TOT (SM_GI + GN * GI_STR)          // 15360 floats = 61440 bytes

// -------- persistent device scratch (no allocations allowed) --------
__device__ float g_Hemb[BS * NN * EMB];
__device__ float g_gi[BS * NN * 3 * HIDN];   // input-side GRU gates (batched)
__device__ float g_hall[BS * NN * HIDN];
__device__ float g_P[BS * NN * HIDN];
__device__ float g_Q[BS * NN * HIDN];
__device__ float g_xh[BS * NN * EMB];
__device__ float g_as[BS * NN * NH];
__device__ float g_ad[BS * NN * NH];
__device__ int   g_kdst[BS * NN * KS];
__device__ float g_kw[BS * NN * KS];
__device__ float g_kex[BS * NN * KS * NH];
__device__ float g_ssum[BS * NN * NH];
__device__ float g_Aval[BS * NN * KS * NH];  // normalized, dedup-merged A entries
__device__ int   g_Adst[BS * NN * KS];       // -1 = duplicate slot (skip)

__device__ __forceinline__ float sigm(float x) { return 1.f / (1.f + expf(-x)); }

// ---------------- zero-fill the whole attention output region ----------------
__global__ void zeroA(float* __restrict__ outp) {
    float4* base = (float4*)(outp + ATTN_OFS);
    size_t total = (size_t)BS * NH * NN * NN / 4;
    size_t stride = (size_t)gridDim.x * blockDim.x;
    float4 z = make_float4(0.f, 0.f, 0.f, 0.f);
    for (size_t i = (size_t)blockIdx.x * blockDim.x + threadIdx.x; i < total; i += stride)
        base[i] = z;
}

// ---------------- Obs embedding: Linear-ReLU-Linear-ReLU-LayerNorm ----------------
__global__ void __launch_bounds__(32, 16)
embed_k(const float* __restrict__ Ht,
        const float* __restrict__ We1, const float* __restrict__ be1,
        const float* __restrict__ We2, const float* __restrict__ be2,
        const float* __restrict__ lng, const float* __restrict__ lnb) {
    int r0 = blockIdx.x * RTB;
    int j  = threadIdx.x;  // 0..31
    __shared__ float in_s[RTB][OBSD + 1];
    __shared__ float x1_s[RTB][EMB];

    for (int t = j; t < RTB * OBSD; t += 32)
        in_s[t / OBSD][t % OBSD] = Ht[(size_t)r0 * OBSD + t];
    __syncwarp();

    float a[RTB];
    float b1 = be1[j];
#pragma unroll
    for (int m = 0; m < RTB; m++) a[m] = b1;
#pragma unroll
    for (int k = 0; k < OBSD; k++) {
        float w = We1[k * EMB + j];
#pragma unroll
        for (int m = 0; m < RTB; m++) a[m] += in_s[m][k] * w;
    }
#pragma unroll
    for (int m = 0; m < RTB; m++) x1_s[m][j] = fmaxf(a[m], 0.f);
    __syncwarp();

    float b[RTB];
    float b2 = be2[j];
#pragma unroll
    for (int m = 0; m < RTB; m++) b[m] = b2;
#pragma unroll
    for (int k = 0; k < EMB; k++) {
        float w = We2[k * EMB + j];
#pragma unroll
        for (int m = 0; m < RTB; m++) b[m] += x1_s[m][k] * w;
    }

    float gj = lng[j], bj = lnb[j];
#pragma unroll
    for (int m = 0; m < RTB; m++) {
        float x = fmaxf(b[m], 0.f);
        float s = x;
#pragma unroll
        for (int o = 16; o; o >>= 1) s += __shfl_xor_sync(0xffffffffu, s, o);
        float mu = s * (1.f / 32.f);
        float d  = x - mu;
        float v  = d * d;
#pragma unroll
        for (int o = 16; o; o >>= 1) v += __shfl_xor_sync(0xffffffffu, v, o);
        g_Hemb[(size_t)(r0 + m) * EMB + j] = d * rsqrtf(v * (1.f / 32.f) + 1e-5f) * gj + bj;
    }
}

// ---------------- gi_all: input-side GRU gates for ALL steps (batched) ----------------
__global__ void __launch_bounds__(192, 8)
gi_all(const float* __restrict__ Wih, const float* __restrict__ bih) {
    size_t r0 = (size_t)blockIdx.x * INT;
    int j = threadIdx.x;  // 0..191 -> row of Wih (3H x EMB)
    __shared__ float e_s[INT][EMB];

    for (int t = j; t < INT * EMB; t += 192)
        e_s[t >> 5][t & 31] = g_Hemb[r0 * EMB + t];
    __syncthreads();

    float acc[INT];
    float b = bih[j];
#pragma unroll
    for (int m = 0; m < INT; m++) acc[m] = b;
    const float4* wi = (const float4*)(Wih + (size_t)j * EMB);
#pragma unroll
    for (int k4 = 0; k4 < EMB / 4; k4++) {
        float4 w = wi[k4];
        int k = k4 * 4;
#pragma unroll
        for (int m = 0; m < INT; m++)
            acc[m] += e_s[m][k] * w.x + e_s[m][k + 1] * w.y + e_s[m][k + 2] * w.z + e_s[m][k + 3] * w.w;
    }
#pragma unroll
    for (int m = 0; m < INT; m++)
        g_gi[(r0 + m) * 3 * HIDN + j] = acc[m];
}

// ---------------- gruAll: ALL 8 GRU steps in ONE launch (per-node recurrence) ----------------
__global__ void __launch_bounds__(256, 2)
gruAll(const float* __restrict__ Whh, const float* __restrict__ bhh) {
    extern __shared__ float sm[];
    float* W_s  = sm + SM_W;
    float* b_s  = sm + SM_B;
    float* h_s  = sm + SM_H;
    float* gi_s = sm + SM_GI;

    int n0  = blockIdx.x * GN;
    int tid = threadIdx.x;
    int lane = tid & 31, w = tid >> 5;
    int m  = lane & 7;                 // node within block
    int jb = w * 8 + (lane >> 3) * 2;  // j base; thread covers jb, jb+1

    for (int i = tid; i < 192 * HIDN; i += 256)
        W_s[(i >> 6) * W_STR + (i & 63)] = Whh[i];
    for (int i = tid; i < 192; i += 256) b_s[i] = bhh[i];
    for (int i = tid; i < GN * H_STR; i += 256) h_s[i] = 0.f;
    __syncthreads();

    for (int t = 0; t < BS; t++) {
        size_t gbase = ((size_t)t * NN + n0) * 192;
        for (int i = tid; i < GN * 192; i += 256)
            gi_s[(i / 192) * GI_STR + (i % 192)] = g_gi[gbase + i];
        __syncthreads();

        float a0[2] = {0.f, 0.f}, a1[2] = {0.f, 0.f}, a2[2] = {0.f, 0.f};
        const float* hrow = h_s + m * H_STR;
#pragma unroll
        for (int k4 = 0; k4 < HIDN / 4; k4++) {
            float4 h4 = *(const float4*)(hrow + k4 * 4);
#pragma unroll
            for (int u = 0; u < 2; u++) {
                int j = jb + u;
                float4 w0 = *(const float4*)(W_s + j * W_STR + k4 * 4);
                float4 w1 = *(const float4*)(W_s + (64 + j) * W_STR + k4 * 4);
                float4 w2 = *(const float4*)(W_s + (128 + j) * W_STR + k4 * 4);
                a0[u] += h4.x * w0.x + h4.y * w0.y + h4.z * w0.z + h4.w * w0.w;
                a1[u] += h4.x * w1.x + h4.y * w1.y + h4.z * w1.z + h4.w * w1.w;
                a2[u] += h4.x * w2.x + h4.y * w2.y + h4.z * w2.z + h4.w * w2.w;
            }
        }

        float hnv[2];
#pragma unroll
        for (int u = 0; u < 2; u++) {
            int j = jb + u;
            float r  = sigm(gi_s[m * GI_STR + j]        + a0[u] + b_s[j]);
            float z  = sigm(gi_s[m * GI_STR + 64 + j]   + a1[u] + b_s[64 + j]);
            float nv = tanhf(gi_s[m * GI_STR + 128 + j] + (a2[u] + b_s[128 + j]) * r);
            hnv[u] = (1.f - z) * nv + z * hrow[j];
        }
        __syncthreads();
#pragma unroll
        for (int u = 0; u < 2; u++) h_s[m * H_STR + jb + u] = hnv[u];
        __syncthreads();

        for (int i = tid; i < GN * HIDN; i += 256)
            g_hall[((size_t)t * NN + n0 + (i >> 6)) * HIDN + (i & 63)] = h_s[(i >> 6) * H_STR + (i & 63)];
        __syncthreads();
    }
}

// ---------------- post_all: P/Q/xh/a_s/a_d + inits for ALL steps at once ----------------
// grid = BS*NN/PNT = 384 blocks, 256 threads: group s = tid>>6 (0..3) handles rows r0+s*8..+7,
// thread j = tid&63 computes output channel j. Ws1 staged in shared (32KB).
__global__ void __launch_bounds__(256, 4)
post_k(const float* __restrict__ Ws1, const float* __restrict__ bs1,
       const float* __restrict__ Wgat,
       const float* __restrict__ asrc, const float* __restrict__ adst,
       const float* __restrict__ bgat,
       float* __restrict__ outp) {
    size_t r0 = (size_t)blockIdx.x * PNT;   // flat (t*NN+n) index
    int tid = threadIdx.x;
    int s = tid >> 6, j = tid & 63;
    __shared__ float Ws1_s[2 * HIDN * HIDN];   // 32 KB
    __shared__ float hn_s[PNT][HIDN];          // 8 KB
    __shared__ float xh_s[PNT][EMB];           // 4 KB

    for (int i = tid; i < 2 * HIDN * HIDN; i += 256) Ws1_s[i] = Ws1[i];
    for (int i = tid; i < PNT * HIDN; i += 256)
        hn_s[i >> 6][i & 63] = g_hall[r0 * HIDN + i];
    __syncthreads();

    const int mb = s * 8;  // row base for this group
    float p[8], q[8];
    float bp = bs1[j];
#pragma unroll
    for (int m = 0; m < 8; m++) { p[m] = bp; q[m] = 0.f; }
#pragma unroll 8
    for (int k = 0; k < HIDN; k++) {
        float w1 = Ws1_s[k * HIDN + j];
        float w2 = Ws1_s[(HIDN + k) * HIDN + j];
#pragma unroll
        for (int m = 0; m < 8; m++) {
            float h = hn_s[mb + m][k];
            p[m] += h * w1; q[m] += h * w2;
        }
    }
#pragma unroll
    for (int m = 0; m < 8; m++) {
        g_P[(r0 + mb + m) * HIDN + j] = p[m];
        g_Q[(r0 + mb + m) * HIDN + j] = q[m];
    }

    if (j < EMB) {
        float x[8];
#pragma unroll
        for (int m = 0; m < 8; m++) x[m] = 0.f;
#pragma unroll 8
        for (int k = 0; k < HIDN; k++) {
            float w = Wgat[k * EMB + j];
#pragma unroll
            for (int m = 0; m < 8; m++) x[m] += hn_s[mb + m][k] * w;
        }
        float bg = bgat[j];
#pragma unroll
        for (int m = 0; m < 8; m++) {
            xh_s[mb + m][j] = x[m];
            g_xh[(r0 + mb + m) * EMB + j] = x[m];
            outp[(r0 + mb + m) * EMB + j] = bg;  // segment_sum init + bias
        }
    }
    __syncthreads();

    if (j < 8 * NH) {
        int m = mb + (j >> 2), h = j & 3;
        float as_ = 0.f, ad_ = 0.f;
#pragma unroll
        for (int c = 0; c < CD; c++) {
            as_ += xh_s[m][h * CD + c] * asrc[h * CD + c];
            ad_ += xh_s[m][h * CD + c] * adst[h * CD + c];
        }
        g_as[(r0 + m) * NH + h]   = as_;
        g_ad[(r0 + m) * NH + h]   = ad_;
        g_ssum[(r0 + m) * NH + h] = 0.f;
    }
}

// ---------------- k2_all: edge scores + warp top-k + exp + segment sums ----------------
__global__ void __launch_bounds__(256, 8)
k2_all(const int* __restrict__ dst,
       const float* __restrict__ Ws2, const float* __restrict__ bs2) {
    int warp = threadIdx.x >> 5, lane = threadIdx.x & 31;
    size_t b = (size_t)blockIdx.x * 8 + warp;   // flat (t*NN + n)
    int n = (int)(b % NN);
    size_t tbase = b - n;                        // t*NN

    __shared__ float w2_s[HIDN];
    __shared__ float P_sh[8][HIDN];
    if (threadIdx.x < HIDN) w2_s[threadIdx.x] = Ws2[threadIdx.x];
    P_sh[warp][lane]      = g_P[b * HIDN + lane];
    P_sh[warp][32 + lane] = g_P[b * HIDN + 32 + lane];
    float as0 = g_as[b * NH + 0], as1 = g_as[b * NH + 1];
    float as2 = g_as[b * NH + 2], as3 = g_as[b * NH + 3];
    __syncthreads();

    int d = dst[n * DEG + lane];
    const float4* Qr = (const float4*)(g_Q + (tbase + d) * HIDN);
    float acc = bs2[0];
    const float* P_s = P_sh[warp];
#pragma unroll
    for (int k4 = 0; k4 < HIDN / 4; k4++) {
        float4 qv = Qr[k4];
        int k = k4 * 4;
        acc += fmaxf(P_s[k] + qv.x, 0.f) * w2_s[k]
             + fmaxf(P_s[k + 1] + qv.y, 0.f) * w2_s[k + 1]
             + fmaxf(P_s[k + 2] + qv.z, 0.f) * w2_s[k + 2]
             + fmaxf(P_s[k + 3] + qv.w, 0.f) * w2_s[k + 3];
    }
    float score = sigm(acc);

    // top-k (k=4) among 32 lanes; ties -> lower index (matches jax.lax.top_k)
    bool sel = false;
#pragma unroll
    for (int r = 0; r < KS; r++) {
        float v = sel ? -1e30f : score;
        int   idx = lane;
#pragma unroll
        for (int o = 16; o; o >>= 1) {
            float ov = __shfl_xor_sync(0xffffffffu, v, o);
            int   oi = __shfl_xor_sync(0xffffffffu, idx, o);
            if (ov > v || (ov == v && oi < idx)) { v = ov; idx = oi; }
        }
        if (lane == idx) sel = true;
    }
    unsigned ball = __ballot_sync(0xffffffffu, sel);
    if (sel) {
        int slot = __popc(ball & ((1u << lane) - 1u));
        g_kdst[b * KS + slot] = d;
        g_kw[b * KS + slot]   = score;
        float4 adv = *(const float4*)(g_ad + (tbase + d) * NH);
        float4 ex4;
        float lg;
        lg = as0 + adv.x; lg = lg > 0.f ? lg : 0.2f * lg; ex4.x = expf(lg);
        lg = as1 + adv.y; lg = lg > 0.f ? lg : 0.2f * lg; ex4.y = expf(lg);
        lg = as2 + adv.z; lg = lg > 0.f ? lg : 0.2f * lg; ex4.z = expf(lg);
        lg = as3 + adv.w; lg = lg > 0.f ? lg : 0.2f * lg; ex4.w = expf(lg);
        *(float4*)(g_kex + (b * KS + slot) * NH) = ex4;
        float* ss = g_ssum + (tbase + d) * NH;
        atomicAdd(ss + 0, ex4.x);
        atomicAdd(ss + 1, ex4.y);
        atomicAdd(ss + 2, ex4.z);
        atomicAdd(ss + 3, ex4.w);
    }
}

// ---------------- k4_all: alpha + row-normalize + dedup + out messages ----------------
__global__ void __launch_bounds__(256, 8)
k4_all(float* __restrict__ outp) {
    int warp = threadIdx.x >> 5, lane = threadIdx.x & 31;
    size_t b = (size_t)blockIdx.x * 8 + warp;   // flat (t*NN + n)
    int n = (int)(b % NN);
    size_t tbase = b - n;                        // t*NN
    const unsigned full = 0xffffffffu;
    int i = (lane >> 2) & 3, h = lane & 3;       // lanes 16..31 mirror 0..15

    int   d_i = g_kdst[b * KS + i];
    float w_i = g_kw[b * KS + i];
    float ex  = g_kex[(b * KS + i) * NH + h];
    float alpha = ex / fmaxf(g_ssum[(tbase + d_i) * NH + h], 1e-16f);

    float rs = alpha;
    rs += __shfl_xor_sync(full, rs, 4);
    rs += __shfl_xor_sync(full, rs, 8);
    float rinv = 1.f / fmaxf(rs, 1e-9f);

    bool first = true;
    float acc = alpha;
#pragma unroll
    for (int jj = 0; jj < KS; jj++) {
        int   dj = __shfl_sync(full, d_i,   jj * 4 + h);
        float aj = __shfl_sync(full, alpha, jj * 4 + h);
        if (jj < i && dj == d_i) first = false;
        if (jj > i && dj == d_i) acc += aj;
    }
    if (lane < 16) {
        g_Aval[(b * KS + i) * NH + h] = first ? acc * rinv : 0.f;
        if (h == 0) g_Adst[b * KS + i] = first ? d_i : -1;
    }

    int h2 = lane >> 3, c = lane & 7;
    float xhv = g_xh[b * EMB + h2 * CD + c];
#pragma unroll
    for (int jj = 0; jj < KS; jj++) {
        float a_jh = __shfl_sync(full, alpha, jj * 4 + h2);
        float wj   = __shfl_sync(full, w_i,   jj * 4);
        int   dj   = __shfl_sync(full, d_i,   jj * 4);
        atomicAdd(&outp[(tbase + dj) * EMB + h2 * CD + c], a_jh * xhv * wj);
    }
}

// ---------------- scatterA: write the nonzero attention entries ----------------
__global__ void scatterA(float* __restrict__ outp) {
    int gid = blockIdx.x * blockDim.x + threadIdx.x;
    if (gid >= BS * NN * KS) return;
    int slot = gid & 3;
    size_t b = gid >> 2;          // t*NN + n
    int n = (int)(b % NN);
    int t = (int)(b / NN);
    int d = g_Adst[b * KS + slot];
    if (d < 0) return;
    float4 v = *(const float4*)(g_Aval + (b * KS + slot) * NH);
    float* Abase = outp + ATTN_OFS;
    size_t rowstride = (size_t)NN * NN;
    size_t base = ((size_t)t * NH) * rowstride + (size_t)n * NN + d;
    Abase[base]                 = v.x;
    Abase[base + rowstride]     = v.y;
    Abase[base + 2 * rowstride] = v.z;
    Abase[base + 3 * rowstride] = v.w;
}

// ---------------- launch ----------------
static cudaStream_t make_stream() {
    cudaStream_t s; cudaStreamCreateWithFlags(&s, cudaStreamNonBlocking); return s;
}
static cudaEvent_t make_event() {
    cudaEvent_t e; cudaEventCreateWithFlags(&e, cudaEventDisableTiming); return e;
}

extern "C" void kernel_launch(void* const* d_in, const int* in_sizes, int n_in,
                              void* d_out, int out_size) {
    int base = (in_sizes[3] == 1) ? 4 : 3;  // scalar k may or may not be materialized
    const float* Ht  = (const float*)d_in[0];
    const int*   dst = (const int*)d_in[2];
    const float* We1 = (const float*)d_in[base + 0];
    const float* be1 = (const float*)d_in[base + 1];
    const float* We2 = (const float*)d_in[base + 2];
    const float* be2 = (const float*)d_in[base + 3];
    const float* lng = (const float*)d_in[base + 4];
    const float* lnb = (const float*)d_in[base + 5];
    const float* Wih = (const float*)d_in[base + 6];
    const float* Whh = (const float*)d_in[base + 7];
    const float* bih = (const float*)d_in[base + 8];
    const float* bhh = (const float*)d_in[base + 9];
    const float* Ws1 = (const float*)d_in[base + 10];
    const float* bs1 = (const float*)d_in[base + 11];
    const float* Ws2 = (const float*)d_in[base + 12];
    const float* bs2 = (const float*)d_in[base + 13];
    const float* Wgat = (const float*)d_in[base + 14];
    const float* asrc = (const float*)d_in[base + 15];
    const float* adst = (const float*)d_in[base + 16];
    const float* bgat = (const float*)d_in[base + 17];
    float* outp = (float*)d_out;

    static cudaStream_t s2   = make_stream();
    static cudaEvent_t evF   = make_event();
    static cudaEvent_t evZ   = make_event();

    cudaFuncSetAttribute(gruAll, cudaFuncAttributeMaxDynamicSharedMemorySize, SM_TOT * 4);

    // fork: zeroA streams the attention region in parallel with the compute chain
    cudaEventRecord(evF, 0);
    cudaStreamWaitEvent(s2, evF, 0);
    zeroA<<<4608, 256, 0, s2>>>(outp);
    cudaEventRecord(evZ, s2);

    // main chain (default stream)
    embed_k<<<(BS * NN) / RTB, 32>>>(Ht, We1, be1, We2, be2, lng, lnb);
    gi_all<<<(BS * NN) / INT, 192>>>(Wih, bih);
    gruAll<<<NN / GN, 256, SM_TOT * 4>>>(Whh, bhh);
    post_k<<<(BS * NN) / PNT, 256>>>(Ws1, bs1, Wgat, asrc, adst, bgat, outp);
    k2_all<<<(BS * NN) / 8, 256>>>(dst, Ws2, bs2);
    k4_all<<<(BS * NN) / 8, 256>>>(outp);

    // join: scatter needs both the zeroed A region and k4's alpha slots
    cudaStreamWaitEvent(0, evZ, 0);
    scatterA<<<(BS * NN * KS + 255) / 256, 256>>>(outp);
}